// round 5
// baseline (speedup 1.0000x reference)
#include <cuda_runtime.h>

// PositionEmbeddingEncoder: 1M points, 8 grid levels (2^d per axis),
// gather 8-float embedding row per level, concat -> [N, 64] fp32.
//
// R2: smem-staged coalesced output. Each block of 128 threads handles 128
// points. Threads gather into a bank-conflict-free padded smem tile
// (row stride 68 floats), then the block streams the tile to GMEM with
// perfectly coalesced float4 stores (evict-first policy).

#define SIZE_F     256.0f
#define HALF_SIZE  128.0f
#define EMBED_DIM  8
#define N_DEPTH    8
#define PTS        128          // points (=threads) per block
#define ROW_W      68           // padded row width in floats (64 data + 4 pad)

__global__ __launch_bounds__(PTS)
void pee_kernel(const float* __restrict__ x,
                const float* __restrict__ w1,
                const float* __restrict__ w2,
                const float* __restrict__ w3,
                const float* __restrict__ w4,
                const float* __restrict__ w5,
                const float* __restrict__ w6,
                const float* __restrict__ w7,
                const float* __restrict__ w8,
                float* __restrict__ out,
                int n)
{
    __shared__ float tile[PTS * ROW_W];   // 34,816 B

    const int tl = threadIdx.x;
    const int p  = blockIdx.x * PTS + tl;

    if (p < n) {
        float sx = (x[3 * p + 0] + HALF_SIZE) * (1.0f / SIZE_F);
        float sy = (x[3 * p + 1] + HALF_SIZE) * (1.0f / SIZE_F);
        float sz = (x[3 * p + 2] + HALF_SIZE) * (1.0f / SIZE_F);

        const float* tables[N_DEPTH] = { w1, w2, w3, w4, w5, w6, w7, w8 };

        float4* trow = (float4*)&tile[tl * ROW_W];

#pragma unroll
        for (int d = 1; d <= N_DEPTH; d++) {
            const int   gi = 1 << d;
            const float gf = (float)gi;

            int gx = (int)floorf(sx * gf);
            int gy = (int)floorf(sy * gf);
            int gz = (int)floorf(sz * gf);
            gx = min(max(gx, 0), gi - 1);
            gy = min(max(gy, 0), gi - 1);
            gz = min(max(gz, 0), gi - 1);

            unsigned int flat = (unsigned int)gx
                              + ((unsigned int)gy << d)
                              + ((unsigned int)gz << (2 * d));

            const float4* row = (const float4*)(tables[d - 1] + (size_t)flat * EMBED_DIM);
            float4 a = __ldg(row + 0);
            float4 b = __ldg(row + 1);

            trow[(d - 1) * 2 + 0] = a;
            trow[(d - 1) * 2 + 1] = b;
        }
    }

    __syncthreads();

    // Coalesced write-out: tile is PTS*16 float4s; global layout is linear
    // (point-major, 16 float4 per point). f = pp*16 + c4 maps linearly to
    // the global float4 index, so consecutive threads write consecutive
    // 16-B chunks.
    const int  base_pt = blockIdx.x * PTS;
    float4*    o4      = (float4*)out;

#pragma unroll
    for (int j = 0; j < 16; j++) {
        int f  = j * PTS + tl;
        int pp = f >> 4;          // local point
        int c4 = f & 15;          // float4 column
        int gp = base_pt + pp;
        if (gp < n) {
            float4 v = *(const float4*)&tile[pp * ROW_W + c4 * 4];
            __stcs(&o4[(size_t)gp * 16 + c4], v);
        }
    }
}

extern "C" void kernel_launch(void* const* d_in, const int* in_sizes, int n_in,
                              void* d_out, int out_size)
{
    const float* x  = (const float*)d_in[0];
    const float* w1 = (const float*)d_in[1];
    const float* w2 = (const float*)d_in[2];
    const float* w3 = (const float*)d_in[3];
    const float* w4 = (const float*)d_in[4];
    const float* w5 = (const float*)d_in[5];
    const float* w6 = (const float*)d_in[6];
    const float* w7 = (const float*)d_in[7];
    const float* w8 = (const float*)d_in[8];
    float* out = (float*)d_out;

    int n = in_sizes[0] / 3;
    int blocks = (n + PTS - 1) / PTS;
    pee_kernel<<<blocks, PTS>>>(x, w1, w2, w3, w4, w5, w6, w7, w8, out, n);
}

// round 6
// speedup vs baseline: 2.5202x; 2.5202x over previous
#include <cuda_runtime.h>

// PositionEmbeddingEncoder — wavefront-minimized mapping.
//
// Warp layout: thread t handles (point = pair*2 + (t>>4), depth = ((t>>1)&7)+1,
// half = t&1). One gather LDG.128 per thread per pair-group:
//   - lanes 2k,2k+1 read the two 16B halves of the SAME 32B table row
//     -> 16 distinct 128B lines per instruction (16 wf vs 32).
//   - store offset within point row = (t&15)*16B -> one STG.128 covers two
//     contiguous 256B point rows (4 lines / 4 wf vs 32).
// Each thread batches U=4 independent gathers before storing (MLP).

#define SIZE_F     256.0f
#define HALF_SIZE  128.0f
#define U          4              // point-pairs per warp (unrolled)

__global__ __launch_bounds__(256)
void pee_kernel(const float* __restrict__ x,
                const float* __restrict__ w1,
                const float* __restrict__ w2,
                const float* __restrict__ w3,
                const float* __restrict__ w4,
                const float* __restrict__ w5,
                const float* __restrict__ w6,
                const float* __restrict__ w7,
                const float* __restrict__ w8,
                float* __restrict__ out,
                int n)
{
    const int lane   = threadIdx.x & 31;
    const int warpid = (blockIdx.x * (blockDim.x >> 5)) + (threadIdx.x >> 5);

    const int dm = (lane >> 1) & 7;       // 0..7  -> depth = dm+1
    const int h  = lane & 1;              // row half
    const int ps = lane >> 4;             // 0/1: which point of the pair

    // per-thread table pointer (fixed for whole kernel)
    const float* wp;
    switch (dm) {
        case 0: wp = w1; break;
        case 1: wp = w2; break;
        case 2: wp = w3; break;
        case 3: wp = w4; break;
        case 4: wp = w5; break;
        case 5: wp = w6; break;
        case 6: wp = w7; break;
        default: wp = w8; break;
    }

    const int   depth = dm + 1;
    const int   g     = 1 << depth;
    const float gf    = (float)g;

    const long long pair0 = (long long)warpid * U;

    float4 v[U];
    int    p[U];

#pragma unroll
    for (int u = 0; u < U; u++) {
        long long pr = pair0 + u;
        int pt = (int)(pr * 2) + ps;
        p[u] = pt;
        if (pt < n) {
            float sx = (x[3 * pt + 0] + HALF_SIZE) * (1.0f / SIZE_F);
            float sy = (x[3 * pt + 1] + HALF_SIZE) * (1.0f / SIZE_F);
            float sz = (x[3 * pt + 2] + HALF_SIZE) * (1.0f / SIZE_F);

            int gx = (int)floorf(sx * gf);
            int gy = (int)floorf(sy * gf);
            int gz = (int)floorf(sz * gf);
            gx = min(max(gx, 0), g - 1);
            gy = min(max(gy, 0), g - 1);
            gz = min(max(gz, 0), g - 1);

            unsigned int flat = (unsigned int)gx
                              + ((unsigned int)gy << depth)
                              + ((unsigned int)gz << (2 * depth));

            v[u] = __ldg((const float4*)(wp + (size_t)flat * 8 + h * 4));
        }
    }

#pragma unroll
    for (int u = 0; u < U; u++) {
        if (p[u] < n) {
            // out row: p*64 floats; this thread's slot = (lane&15)*4 floats
            __stcs((float4*)(out + (size_t)p[u] * 64) + (lane & 15), v[u]);
        }
    }
}

extern "C" void kernel_launch(void* const* d_in, const int* in_sizes, int n_in,
                              void* d_out, int out_size)
{
    const float* x  = (const float*)d_in[0];
    const float* w1 = (const float*)d_in[1];
    const float* w2 = (const float*)d_in[2];
    const float* w3 = (const float*)d_in[3];
    const float* w4 = (const float*)d_in[4];
    const float* w5 = (const float*)d_in[5];
    const float* w6 = (const float*)d_in[6];
    const float* w7 = (const float*)d_in[7];
    const float* w8 = (const float*)d_in[8];
    float* out = (float*)d_out;

    int n = in_sizes[0] / 3;

    // one warp covers U pairs = 2*U points; 8 warps per block
    int pts_per_block = 8 * U * 2;                   // 64
    int blocks = (n + pts_per_block - 1) / pts_per_block;
    pee_kernel<<<blocks, 256>>>(x, w1, w2, w3, w4, w5, w6, w7, w8, out, n);
}